// round 13
// baseline (speedup 1.0000x reference)
#include <cuda_runtime.h>
#include <cstdint>
#include <cstddef>

#define NN   8192
#define DIN  512
#define DH   256
#define DOUT 128
#define CAP  256
#define SLOPE 0.25f
#define FULL 0xffffffffu

// ---- scratch (static device globals; no allocation allowed) ----
__device__ int      g_cols[(size_t)NN * CAP];
__device__ float    g_vals[(size_t)NN * CAP];
__device__ int      g_nnz[NN];
__device__ float    g_t[(size_t)NN * DH];        // fp32 GEMM outputs (t1/t2)
__device__ float    g_h[(size_t)NN * DOUT];
__device__ float    g_s1p[2][NN];
__device__ float    g_s2p[2][NN];
// pre-split tf32 hi/lo operand buffers
__device__ unsigned g_xh[(size_t)NN * DIN],  g_xl[(size_t)NN * DIN];
__device__ unsigned g_W1h[DIN * DH],  g_W1l[DIN * DH];
__device__ unsigned g_W2h[DH * DH],   g_W2l[DH * DH];
__device__ unsigned g_Wgh[DH * DOUT], g_Wgl[DH * DOUT];
__device__ unsigned g_oph[(size_t)NN * DH], g_opl[(size_t)NN * DH];  // spmm out hi/lo

__device__ __forceinline__ float leaky(float x) { return x >= 0.f ? x : SLOPE * x; }

__device__ __forceinline__ unsigned f2tf32(float x) {
    unsigned r;
    asm("cvt.rna.tf32.f32 %0, %1;" : "=r"(r) : "f"(x));
    return r;
}

__device__ __forceinline__ void mma_tf32(float* d, const unsigned* a, const unsigned* b) {
    asm volatile(
        "mma.sync.aligned.m16n8k8.row.col.f32.tf32.tf32.f32 "
        "{%0,%1,%2,%3}, {%4,%5,%6,%7}, {%8,%9}, {%0,%1,%2,%3};"
        : "+f"(d[0]), "+f"(d[1]), "+f"(d[2]), "+f"(d[3])
        : "r"(a[0]), "r"(a[1]), "r"(a[2]), "r"(a[3]), "r"(b[0]), "r"(b[1]));
}

// ---------------------------------------------------------------------------
// One-shot hi/lo tf32 split of x, W1, W2, Wg (removes all cvt from GEMM loop).
// ---------------------------------------------------------------------------
#define X4V  (NN * DIN / 4)
#define W14V (DIN * DH / 4)
#define W24V (DH * DH / 4)
#define WG4V (DH * DOUT / 4)
#define CVT_BLOCKS ((X4V + W14V + W24V + WG4V) / 256)

__global__ __launch_bounds__(256) void cvt_split(
    const float4* __restrict__ x,  const float4* __restrict__ w1,
    const float4* __restrict__ w2, const float4* __restrict__ wg)
{
    int i = blockIdx.x * 256 + threadIdx.x;
    const float4* s; uint4 *h, *l; int off;
    if (i < X4V)                     { s = x;  h = (uint4*)g_xh;  l = (uint4*)g_xl;  off = i; }
    else if (i < X4V + W14V)         { s = w1; h = (uint4*)g_W1h; l = (uint4*)g_W1l; off = i - X4V; }
    else if (i < X4V + W14V + W24V)  { s = w2; h = (uint4*)g_W2h; l = (uint4*)g_W2l; off = i - X4V - W14V; }
    else                             { s = wg; h = (uint4*)g_Wgh; l = (uint4*)g_Wgl; off = i - X4V - W14V - W24V; }
    float4 v = s[off];
    uint4 hh, ll;
    hh.x = f2tf32(v.x); ll.x = f2tf32(v.x - __uint_as_float(hh.x));
    hh.y = f2tf32(v.y); ll.y = f2tf32(v.y - __uint_as_float(hh.y));
    hh.z = f2tf32(v.z); ll.z = f2tf32(v.z - __uint_as_float(hh.z));
    hh.w = f2tf32(v.w); ll.w = f2tf32(v.w - __uint_as_float(hh.w));
    h[off] = hh; l[off] = ll;
}

// ---------------------------------------------------------------------------
// 3xTF32 tensor GEMM on pre-split hi/lo operands. CTA 128x64, 8 warps
// (4m x 2n), warp tile 32x32 (2x4 m16n8k8). BK=8, double-buffered.
// A smem column index remapped so (m, m+8) are adjacent  -> LDS.64 frags.
// B smem fragment-major [lane][reg]                      -> LDS.64 frags.
// Inner loop: 16 LDS.64 + 24 mma + pure LDG/STS staging (no cvt).
// ---------------------------------------------------------------------------
__device__ __forceinline__ int m2map(int m) {
    return (m & ~15) | ((m & 7) << 1) | ((m >> 3) & 1);
}

template<bool SCORES>
__global__ __launch_bounds__(256) void gemm_tf32(
    const unsigned* __restrict__ Ag_h, const unsigned* __restrict__ Ag_l,
    const unsigned* __restrict__ Bg_h, const unsigned* __restrict__ Bg_l,
    float* __restrict__ C, int K, int N, const float* __restrict__ avec)
{
    __shared__ unsigned Ah[2][8][136], Al[2][8][136];   // [buf][k][m2]
    __shared__ unsigned BFh[2][2][4][64], BFl[2][2][4][64]; // [buf][wc][nt][lane*2+reg]
    __shared__ float sc1[128][2], sc2[128][2];

    int tid  = threadIdx.x;
    int warp = tid >> 5, lane = tid & 31;
    int g = lane >> 2, tig = lane & 3;
    int wm = (warp >> 1) * 32, wc = warp & 1;
    int m0 = blockIdx.y * 128, n0 = blockIdx.x * 64;

    // staging indices
    int arow = tid >> 1, kq = (tid & 1) * 4;
    int m2a  = m2map(arow);
    const uint4* Aph = (const uint4*)(Ag_h + (size_t)(m0 + arow) * K + kq);
    const uint4* Apl = (const uint4*)(Ag_l + (size_t)(m0 + arow) * K + kq);
    int brow = tid >> 5, bn = (tid & 31) * 2;
    const unsigned* Bph = Bg_h + (size_t)brow * N + n0 + bn;
    const unsigned* Bpl = Bg_l + (size_t)brow * N + n0 + bn;
    // B fragment-major destination for this thread's two columns
    int bwc0 = bn >> 5,        bnt0 = (bn >> 3) & 3;
    int bl0  = (((bn & 7) * 4 + (brow & 3)) << 1) + (brow >> 2);
    int bn1  = bn + 1;
    int bwc1 = bn1 >> 5,       bnt1 = (bn1 >> 3) & 3;
    int bl1  = (((bn1 & 7) * 4 + (brow & 3)) << 1) + (brow >> 2);

    // prologue -> buf 0
    uint4 avh = Aph[0], avl = Apl[0];
    uint2 bvh = *(const uint2*)Bph, bvl = *(const uint2*)Bpl;
    {
        unsigned* ah4 = (unsigned*)&avh; unsigned* al4 = (unsigned*)&avl;
#pragma unroll
        for (int j = 0; j < 4; j++) {
            Ah[0][kq + j][m2a] = ah4[j];
            Al[0][kq + j][m2a] = al4[j];
        }
        BFh[0][bwc0][bnt0][bl0] = bvh.x; BFl[0][bwc0][bnt0][bl0] = bvl.x;
        BFh[0][bwc1][bnt1][bl1] = bvh.y; BFl[0][bwc1][bnt1][bl1] = bvl.y;
    }
    __syncthreads();

    float d[2][4][4];
#pragma unroll
    for (int mt = 0; mt < 2; mt++)
#pragma unroll
        for (int nt = 0; nt < 4; nt++)
#pragma unroll
            for (int i = 0; i < 4; i++) d[mt][nt][i] = 0.f;

    int ktiles = K >> 3;
    for (int tk = 0; tk < ktiles; tk++) {
        int buf = tk & 1;
        if (tk + 1 < ktiles) {
            avh = Aph[(tk + 1) * 2];          // +8 k's = 2 uint4
            avl = Apl[(tk + 1) * 2];
            bvh = *(const uint2*)(Bph + (size_t)(tk + 1) * 8 * N);
            bvl = *(const uint2*)(Bpl + (size_t)(tk + 1) * 8 * N);
        }

        unsigned ah[2][4], al[2][4], bh[4][2], bl[4][2];
#pragma unroll
        for (int mt = 0; mt < 2; mt++) {
            int mb = wm + mt * 16 + (g << 1);
            uint2 h0 = *(uint2*)&Ah[buf][tig][mb];
            uint2 h1 = *(uint2*)&Ah[buf][tig + 4][mb];
            uint2 l0 = *(uint2*)&Al[buf][tig][mb];
            uint2 l1 = *(uint2*)&Al[buf][tig + 4][mb];
            ah[mt][0] = h0.x; ah[mt][1] = h0.y; ah[mt][2] = h1.x; ah[mt][3] = h1.y;
            al[mt][0] = l0.x; al[mt][1] = l0.y; al[mt][2] = l1.x; al[mt][3] = l1.y;
        }
#pragma unroll
        for (int nt = 0; nt < 4; nt++) {
            uint2 b0 = *(uint2*)&BFh[buf][wc][nt][lane * 2];
            uint2 b1 = *(uint2*)&BFl[buf][wc][nt][lane * 2];
            bh[nt][0] = b0.x; bh[nt][1] = b0.y;
            bl[nt][0] = b1.x; bl[nt][1] = b1.y;
        }
#pragma unroll
        for (int mt = 0; mt < 2; mt++)
#pragma unroll
            for (int nt = 0; nt < 4; nt++) {
                mma_tf32(d[mt][nt], ah[mt], bh[nt]);
                mma_tf32(d[mt][nt], ah[mt], bl[nt]);
                mma_tf32(d[mt][nt], al[mt], bh[nt]);
            }

        if (tk + 1 < ktiles) {
            int nb = buf ^ 1;
            unsigned* ah4 = (unsigned*)&avh; unsigned* al4 = (unsigned*)&avl;
#pragma unroll
            for (int j = 0; j < 4; j++) {
                Ah[nb][kq + j][m2a] = ah4[j];
                Al[nb][kq + j][m2a] = al4[j];
            }
            BFh[nb][bwc0][bnt0][bl0] = bvh.x; BFl[nb][bwc0][bnt0][bl0] = bvl.x;
            BFh[nb][bwc1][bnt1][bl1] = bvh.y; BFl[nb][bwc1][bnt1][bl1] = bvl.y;
        }
        __syncthreads();
    }

    int wn = wc * 32;
#pragma unroll
    for (int mt = 0; mt < 2; mt++) {
#pragma unroll
        for (int nt = 0; nt < 4; nt++) {
            int r0 = m0 + wm + mt * 16 + g;
            int cc = n0 + wn + nt * 8 + 2 * tig;
            float2 lo = { d[mt][nt][0], d[mt][nt][1] };
            float2 hi = { d[mt][nt][2], d[mt][nt][3] };
            *reinterpret_cast<float2*>(&C[(size_t)r0 * N + cc])       = lo;
            *reinterpret_cast<float2*>(&C[(size_t)(r0 + 8) * N + cc]) = hi;
        }
    }

    if (SCORES) {
#pragma unroll
        for (int mt = 0; mt < 2; mt++) {
#pragma unroll
            for (int h = 0; h < 2; h++) {
                float l1 = 0.f, l2 = 0.f;
#pragma unroll
                for (int nt = 0; nt < 4; nt++) {
                    int cc = n0 + wn + nt * 8 + 2 * tig;
                    float c0 = d[mt][nt][2 * h], c1 = d[mt][nt][2 * h + 1];
                    l1 += c0 * avec[cc] + c1 * avec[cc + 1];
                    l2 += c0 * avec[DOUT + cc] + c1 * avec[DOUT + cc + 1];
                }
                l1 += __shfl_xor_sync(FULL, l1, 1);
                l1 += __shfl_xor_sync(FULL, l1, 2);
                l2 += __shfl_xor_sync(FULL, l2, 1);
                l2 += __shfl_xor_sync(FULL, l2, 2);
                if (tig == 0) {
                    int rl = wm + mt * 16 + g + 8 * h;
                    sc1[rl][wc] = l1;
                    sc2[rl][wc] = l2;
                }
            }
        }
        __syncthreads();
        if (tid < 128) {
            g_s1p[blockIdx.x][m0 + tid] = sc1[tid][0] + sc1[tid][1];
            g_s2p[blockIdx.x][m0 + tid] = sc2[tid][0] + sc2[tid][1];
        }
    }
}

// ---------------------------------------------------------------------------
// Build padded CSR. One block/row, 256 thr, coalesced strided loads.
// ---------------------------------------------------------------------------
__global__ void build_csr(const float* __restrict__ adj) {
    int row = blockIdx.x;
    int t   = threadIdx.x;
    int lane = t & 31, warp = t >> 5;
    const float4* arow = reinterpret_cast<const float4*>(adj + (size_t)row * NN);

    float4 v[8];
    int cnt = 0;
#pragma unroll
    for (int i = 0; i < 8; i++) {
        v[i] = arow[t + i * 256];
        cnt += (v[i].x > 0.f) + (v[i].y > 0.f) + (v[i].z > 0.f) + (v[i].w > 0.f);
    }

    int inc = cnt;
#pragma unroll
    for (int o = 1; o < 32; o <<= 1) {
        int u = __shfl_up_sync(FULL, inc, o);
        if (lane >= o) inc += u;
    }
    __shared__ int wsum[8], wbase[8];
    if (lane == 31) wsum[warp] = inc;
    __syncthreads();
    if (t == 0) {
        int run = 0;
#pragma unroll
        for (int w = 0; w < 8; w++) { wbase[w] = run; run += wsum[w]; }
        g_nnz[row] = run < CAP ? run : CAP;
    }
    __syncthreads();

    int pos = wbase[warp] + inc - cnt;
    int*   cr = g_cols + (size_t)row * CAP;
    float* vr = g_vals + (size_t)row * CAP;
#pragma unroll
    for (int i = 0; i < 8; i++) {
        int base = (t + i * 256) * 4;
        float vv[4] = { v[i].x, v[i].y, v[i].z, v[i].w };
#pragma unroll
        for (int j = 0; j < 4; j++) {
            if (vv[j] > 0.f) {
                if (pos < CAP) { cr[pos] = base + j; vr[pos] = vv[j]; }
                pos++;
            }
        }
    }
}

// ---------------------------------------------------------------------------
// Barrier-free SpMM + bias + leaky; emits tf32 hi/lo pairs directly
// (consumed only by the next GEMM's A operand).
// ---------------------------------------------------------------------------
__global__ __launch_bounds__(128) void spmm_leaky(
    const float* __restrict__ T, const float* __restrict__ bias,
    unsigned* __restrict__ Oh, unsigned* __restrict__ Ol)
{
    int row = blockIdx.x * 2 + (threadIdx.x >> 6);
    int l   = threadIdx.x & 63;
    int nnz = g_nnz[row];
    const int*   cp = g_cols + (size_t)row * CAP;
    const float* vp = g_vals + (size_t)row * CAP;

    float4 a0 = {0,0,0,0}, a1 = {0,0,0,0}, a2 = {0,0,0,0}, a3 = {0,0,0,0};
    int k = 0;
    for (; k + 3 < nnz; k += 4) {
        int   c0 = cp[k], c1 = cp[k+1], c2 = cp[k+2], c3 = cp[k+3];
        float w0 = vp[k], w1 = vp[k+1], w2 = vp[k+2], w3 = vp[k+3];
        float4 v0 = reinterpret_cast<const float4*>(T + (size_t)c0 * DH)[l];
        float4 v1 = reinterpret_cast<const float4*>(T + (size_t)c1 * DH)[l];
        float4 v2 = reinterpret_cast<const float4*>(T + (size_t)c2 * DH)[l];
        float4 v3 = reinterpret_cast<const float4*>(T + (size_t)c3 * DH)[l];
        a0.x += w0*v0.x; a0.y += w0*v0.y; a0.z += w0*v0.z; a0.w += w0*v0.w;
        a1.x += w1*v1.x; a1.y += w1*v1.y; a1.z += w1*v1.z; a1.w += w1*v1.w;
        a2.x += w2*v2.x; a2.y += w2*v2.y; a2.z += w2*v2.z; a2.w += w2*v2.w;
        a3.x += w3*v3.x; a3.y += w3*v3.y; a3.z += w3*v3.z; a3.w += w3*v3.w;
    }
    for (; k < nnz; k++) {
        int c0 = cp[k]; float w0 = vp[k];
        float4 v0 = reinterpret_cast<const float4*>(T + (size_t)c0 * DH)[l];
        a0.x += w0*v0.x; a0.y += w0*v0.y; a0.z += w0*v0.z; a0.w += w0*v0.w;
    }
    float4 b = reinterpret_cast<const float4*>(bias)[l];
    float4 o;
    o.x = leaky(a0.x + a1.x + a2.x + a3.x + b.x);
    o.y = leaky(a0.y + a1.y + a2.y + a3.y + b.y);
    o.z = leaky(a0.z + a1.z + a2.z + a3.z + b.z);
    o.w = leaky(a0.w + a1.w + a2.w + a3.w + b.w);
    uint4 hh, ll;
    hh.x = f2tf32(o.x); ll.x = f2tf32(o.x - __uint_as_float(hh.x));
    hh.y = f2tf32(o.y); ll.y = f2tf32(o.y - __uint_as_float(hh.y));
    hh.z = f2tf32(o.z); ll.z = f2tf32(o.z - __uint_as_float(hh.z));
    hh.w = f2tf32(o.w); ll.w = f2tf32(o.w - __uint_as_float(hh.w));
    reinterpret_cast<uint4*>(Oh + (size_t)row * DH)[l] = hh;
    reinterpret_cast<uint4*>(Ol + (size_t)row * DH)[l] = ll;
}

// ---------------------------------------------------------------------------
// Warp-per-row sparse attention (exact match of dense masked softmax).
// ---------------------------------------------------------------------------
__global__ __launch_bounds__(256) void attn_k(float* __restrict__ out) {
    int warp = threadIdx.x >> 5, l = threadIdx.x & 31;
    int row  = blockIdx.x * 8 + warp;
    int nnz  = g_nnz[row];

    __shared__ float sw[8][CAP];
    __shared__ int   sc[8][CAP];
    float* w = sw[warp];
    int*   c = sc[warp];

    float4 o;
    if (nnz == 0) {
        float4 s = {0,0,0,0};
        for (int r = 0; r < NN; r++) {
            float4 hv = reinterpret_cast<const float4*>(g_h + (size_t)r * DOUT)[l];
            s.x += hv.x; s.y += hv.y; s.z += hv.z; s.w += hv.w;
        }
        float inv = 1.f / (float)NN;
        o.x = leaky(s.x * inv); o.y = leaky(s.y * inv);
        o.z = leaky(s.z * inv); o.w = leaky(s.w * inv);
    } else {
        float s1i = g_s1p[0][row] + g_s1p[1][row];
        const int* cp = g_cols + (size_t)row * CAP;
        float m = -3.0e38f;
        for (int k = l; k < nnz; k += 32) {
            int cj = cp[k];
            float e = leaky(s1i + (g_s2p[0][cj] + g_s2p[1][cj]));
            c[k] = cj; w[k] = e;
            m = fmaxf(m, e);
        }
        __syncwarp();
#pragma unroll
        for (int off = 16; off > 0; off >>= 1)
            m = fmaxf(m, __shfl_xor_sync(FULL, m, off));
        float s = 0.f;
        for (int k = l; k < nnz; k += 32) {
            float e = expf(w[k] - m);
            w[k] = e; s += e;
        }
        __syncwarp();
#pragma unroll
        for (int off = 16; off > 0; off >>= 1)
            s += __shfl_xor_sync(FULL, s, off);
        float inv = 1.f / s;

        float4 a0 = {0,0,0,0}, a1 = {0,0,0,0};
        int k = 0;
        for (; k + 1 < nnz; k += 2) {
            float w0 = w[k], w1 = w[k+1];
            float4 v0 = reinterpret_cast<const float4*>(g_h + (size_t)c[k]   * DOUT)[l];
            float4 v1 = reinterpret_cast<const float4*>(g_h + (size_t)c[k+1] * DOUT)[l];
            a0.x += w0*v0.x; a0.y += w0*v0.y; a0.z += w0*v0.z; a0.w += w0*v0.w;
            a1.x += w1*v1.x; a1.y += w1*v1.y; a1.z += w1*v1.z; a1.w += w1*v1.w;
        }
        if (k < nnz) {
            float w0 = w[k];
            float4 v0 = reinterpret_cast<const float4*>(g_h + (size_t)c[k] * DOUT)[l];
            a0.x += w0*v0.x; a0.y += w0*v0.y; a0.z += w0*v0.z; a0.w += w0*v0.w;
        }
        o.x = leaky((a0.x + a1.x) * inv);
        o.y = leaky((a0.y + a1.y) * inv);
        o.z = leaky((a0.z + a1.z) * inv);
        o.w = leaky((a0.w + a1.w) * inv);
    }
    if (l < 16)
        *reinterpret_cast<float4*>(out + (size_t)row * 64 + l * 4) = o;
    else
        *reinterpret_cast<float4*>(out + (size_t)NN * 64 + (size_t)row * 64 + (l * 4 - 64)) = o;
}

// ---------------------------------------------------------------------------
extern "C" void kernel_launch(void* const* d_in, const int* in_sizes, int n_in,
                              void* d_out, int out_size)
{
    const float* x   = (const float*)d_in[0];
    const float* adj = (const float*)d_in[1];
    const float* W1  = (const float*)d_in[2];
    const float* b1  = (const float*)d_in[3];
    const float* W2  = (const float*)d_in[4];
    const float* b2  = (const float*)d_in[5];
    const float* Wg  = (const float*)d_in[6];
    const float* a   = (const float*)d_in[7];

    float *pT, *pH;
    unsigned *pxh, *pxl, *pw1h, *pw1l, *pw2h, *pw2l, *pwgh, *pwgl, *poph, *popl;
    cudaGetSymbolAddress((void**)&pT,   g_t);
    cudaGetSymbolAddress((void**)&pH,   g_h);
    cudaGetSymbolAddress((void**)&pxh,  g_xh);
    cudaGetSymbolAddress((void**)&pxl,  g_xl);
    cudaGetSymbolAddress((void**)&pw1h, g_W1h);
    cudaGetSymbolAddress((void**)&pw1l, g_W1l);
    cudaGetSymbolAddress((void**)&pw2h, g_W2h);
    cudaGetSymbolAddress((void**)&pw2l, g_W2l);
    cudaGetSymbolAddress((void**)&pwgh, g_Wgh);
    cudaGetSymbolAddress((void**)&pwgl, g_Wgl);
    cudaGetSymbolAddress((void**)&poph, g_oph);
    cudaGetSymbolAddress((void**)&popl, g_opl);

    build_csr<<<NN, 256>>>(adj);
    cvt_split<<<CVT_BLOCKS, 256>>>((const float4*)x, (const float4*)W1,
                                   (const float4*)W2, (const float4*)Wg);
    // t1 = x @ W1
    gemm_tf32<false><<<dim3(DH / 64, NN / 128), 256>>>(
        pxh, pxl, pw1h, pw1l, pT, DIN, DH, nullptr);
    // x1 = leaky(adj @ t1 + b1) -> hi/lo
    spmm_leaky<<<NN / 2, 128>>>(pT, b1, poph, popl);
    // t2 = x1 @ W2
    gemm_tf32<false><<<dim3(DH / 64, NN / 128), 256>>>(
        poph, popl, pw2h, pw2l, pT, DH, DH, nullptr);
    // x2 = leaky(adj @ t2 + b2) -> hi/lo
    spmm_leaky<<<NN / 2, 128>>>(pT, b2, poph, popl);
    // h = x2 @ Wg + fused per-half s1/s2 scores
    gemm_tf32<true><<<dim3(2, NN / 128), 256>>>(
        poph, popl, pwgh, pwgl, pH, DH, DOUT, a);
    // softmax-weighted gather + output
    attn_k<<<NN / 8, 256>>>((float*)d_out);
}

// round 14
// speedup vs baseline: 1.1823x; 1.1823x over previous
#include <cuda_runtime.h>
#include <cstdint>
#include <cstddef>

#define NN   8192
#define DIN  512
#define DH   256
#define DOUT 128
#define CAP  256
#define SLOPE 0.25f
#define FULL 0xffffffffu

// ---- scratch (static device globals; no allocation allowed) ----
__device__ int      g_cols[(size_t)NN * CAP];
__device__ float    g_vals[(size_t)NN * CAP];
__device__ int      g_nnz[NN];
__device__ float    g_t[(size_t)NN * DH];        // fp32 GEMM outputs (t1/t2)
__device__ float    g_h[(size_t)NN * DOUT];
__device__ float    g_s1p[2][NN];
__device__ float    g_s2p[2][NN];
// pre-split tf32 hi/lo operand buffers
__device__ unsigned g_xh[(size_t)NN * DIN],  g_xl[(size_t)NN * DIN];
__device__ unsigned g_W1h[DIN * DH],  g_W1l[DIN * DH];
__device__ unsigned g_W2h[DH * DH],   g_W2l[DH * DH];
__device__ unsigned g_Wgh[DH * DOUT], g_Wgl[DH * DOUT];
__device__ unsigned g_oph[(size_t)NN * DH], g_opl[(size_t)NN * DH];  // spmm out hi/lo

__device__ __forceinline__ float leaky(float x) { return x >= 0.f ? x : SLOPE * x; }

__device__ __forceinline__ unsigned f2tf32(float x) {
    unsigned r;
    asm("cvt.rna.tf32.f32 %0, %1;" : "=r"(r) : "f"(x));
    return r;
}

__device__ __forceinline__ void mma_tf32(float* d, const unsigned* a, const unsigned* b) {
    asm volatile(
        "mma.sync.aligned.m16n8k8.row.col.f32.tf32.tf32.f32 "
        "{%0,%1,%2,%3}, {%4,%5,%6,%7}, {%8,%9}, {%0,%1,%2,%3};"
        : "+f"(d[0]), "+f"(d[1]), "+f"(d[2]), "+f"(d[3])
        : "r"(a[0]), "r"(a[1]), "r"(a[2]), "r"(a[3]), "r"(b[0]), "r"(b[1]));
}

// ---------------------------------------------------------------------------
// One-shot hi/lo tf32 split of x, W1, W2, Wg (removes all cvt from GEMM loop).
// ---------------------------------------------------------------------------
#define X4V  (NN * DIN / 4)
#define W14V (DIN * DH / 4)
#define W24V (DH * DH / 4)
#define WG4V (DH * DOUT / 4)
#define CVT_BLOCKS ((X4V + W14V + W24V + WG4V) / 256)

__global__ __launch_bounds__(256) void cvt_split(
    const float4* __restrict__ x,  const float4* __restrict__ w1,
    const float4* __restrict__ w2, const float4* __restrict__ wg)
{
    int i = blockIdx.x * 256 + threadIdx.x;
    const float4* s; uint4 *h, *l; int off;
    if (i < X4V)                     { s = x;  h = (uint4*)g_xh;  l = (uint4*)g_xl;  off = i; }
    else if (i < X4V + W14V)         { s = w1; h = (uint4*)g_W1h; l = (uint4*)g_W1l; off = i - X4V; }
    else if (i < X4V + W14V + W24V)  { s = w2; h = (uint4*)g_W2h; l = (uint4*)g_W2l; off = i - X4V - W14V; }
    else                             { s = wg; h = (uint4*)g_Wgh; l = (uint4*)g_Wgl; off = i - X4V - W14V - W24V; }
    float4 v = s[off];
    uint4 hh, ll;
    hh.x = f2tf32(v.x); ll.x = f2tf32(v.x - __uint_as_float(hh.x));
    hh.y = f2tf32(v.y); ll.y = f2tf32(v.y - __uint_as_float(hh.y));
    hh.z = f2tf32(v.z); ll.z = f2tf32(v.z - __uint_as_float(hh.z));
    hh.w = f2tf32(v.w); ll.w = f2tf32(v.w - __uint_as_float(hh.w));
    h[off] = hh; l[off] = ll;
}

// ---------------------------------------------------------------------------
// 3xTF32 tensor GEMM on pre-split hi/lo operands. CTA 128x64, 8 warps
// (4m x 2n), warp tile 32x32 (2x4 m16n8k8). BK=8, double-buffered.
// A smem column index remapped so (m, m+8) are adjacent  -> LDS.64 frags.
// B smem fragment-major [wc][nt][lane*2+reg], PADDED to 66 words per
// sub-array so staging STS banks are 16(lane&3)+2*nt+8*wc (2-way max;
// the unpadded 64-word version was a 16-way conflict -> R13 regression).
// Fragment reads: 16-lane phases cover all 32 banks -> conflict-free.
// ---------------------------------------------------------------------------
__device__ __forceinline__ int m2map(int m) {
    return (m & ~15) | ((m & 7) << 1) | ((m >> 3) & 1);
}

template<bool SCORES>
__global__ __launch_bounds__(256) void gemm_tf32(
    const unsigned* __restrict__ Ag_h, const unsigned* __restrict__ Ag_l,
    const unsigned* __restrict__ Bg_h, const unsigned* __restrict__ Bg_l,
    float* __restrict__ C, int K, int N, const float* __restrict__ avec)
{
    __shared__ unsigned Ah[2][8][136], Al[2][8][136];       // [buf][k][m2]
    __shared__ unsigned BFh[2][2][4][66], BFl[2][2][4][66]; // [buf][wc][nt][66: lane*2+reg]
    __shared__ float sc1[128][2], sc2[128][2];

    int tid  = threadIdx.x;
    int warp = tid >> 5, lane = tid & 31;
    int g = lane >> 2, tig = lane & 3;
    int wm = (warp >> 1) * 32, wc = warp & 1;
    int m0 = blockIdx.y * 128, n0 = blockIdx.x * 64;

    // staging indices
    int arow = tid >> 1, kq = (tid & 1) * 4;
    int m2a  = m2map(arow);
    const uint4* Aph = (const uint4*)(Ag_h + (size_t)(m0 + arow) * K + kq);
    const uint4* Apl = (const uint4*)(Ag_l + (size_t)(m0 + arow) * K + kq);
    int brow = tid >> 5, bn = (tid & 31) * 2;
    const unsigned* Bph = Bg_h + (size_t)brow * N + n0 + bn;
    const unsigned* Bpl = Bg_l + (size_t)brow * N + n0 + bn;
    // B fragment-major destination for this thread's two columns
    int bwc0 = bn >> 5,        bnt0 = (bn >> 3) & 3;
    int bl0  = (((bn & 7) * 4 + (brow & 3)) << 1) + (brow >> 2);
    int bn1  = bn + 1;
    int bwc1 = bn1 >> 5,       bnt1 = (bn1 >> 3) & 3;
    int bl1  = (((bn1 & 7) * 4 + (brow & 3)) << 1) + (brow >> 2);

    // prologue -> buf 0
    uint4 avh = Aph[0], avl = Apl[0];
    uint2 bvh = *(const uint2*)Bph, bvl = *(const uint2*)Bpl;
    {
        unsigned* ah4 = (unsigned*)&avh; unsigned* al4 = (unsigned*)&avl;
#pragma unroll
        for (int j = 0; j < 4; j++) {
            Ah[0][kq + j][m2a] = ah4[j];
            Al[0][kq + j][m2a] = al4[j];
        }
        BFh[0][bwc0][bnt0][bl0] = bvh.x; BFl[0][bwc0][bnt0][bl0] = bvl.x;
        BFh[0][bwc1][bnt1][bl1] = bvh.y; BFl[0][bwc1][bnt1][bl1] = bvl.y;
    }
    __syncthreads();

    float d[2][4][4];
#pragma unroll
    for (int mt = 0; mt < 2; mt++)
#pragma unroll
        for (int nt = 0; nt < 4; nt++)
#pragma unroll
            for (int i = 0; i < 4; i++) d[mt][nt][i] = 0.f;

    int ktiles = K >> 3;
    for (int tk = 0; tk < ktiles; tk++) {
        int buf = tk & 1;
        if (tk + 1 < ktiles) {
            avh = Aph[(tk + 1) * 2];
            avl = Apl[(tk + 1) * 2];
            bvh = *(const uint2*)(Bph + (size_t)(tk + 1) * 8 * N);
            bvl = *(const uint2*)(Bpl + (size_t)(tk + 1) * 8 * N);
        }

        unsigned ah[2][4], al[2][4], bh[4][2], bl[4][2];
#pragma unroll
        for (int mt = 0; mt < 2; mt++) {
            int mb = wm + mt * 16 + (g << 1);
            uint2 h0 = *(uint2*)&Ah[buf][tig][mb];
            uint2 h1 = *(uint2*)&Ah[buf][tig + 4][mb];
            uint2 l0 = *(uint2*)&Al[buf][tig][mb];
            uint2 l1 = *(uint2*)&Al[buf][tig + 4][mb];
            ah[mt][0] = h0.x; ah[mt][1] = h0.y; ah[mt][2] = h1.x; ah[mt][3] = h1.y;
            al[mt][0] = l0.x; al[mt][1] = l0.y; al[mt][2] = l1.x; al[mt][3] = l1.y;
        }
#pragma unroll
        for (int nt = 0; nt < 4; nt++) {
            uint2 b0 = *(uint2*)&BFh[buf][wc][nt][lane * 2];
            uint2 b1 = *(uint2*)&BFl[buf][wc][nt][lane * 2];
            bh[nt][0] = b0.x; bh[nt][1] = b0.y;
            bl[nt][0] = b1.x; bl[nt][1] = b1.y;
        }
#pragma unroll
        for (int mt = 0; mt < 2; mt++)
#pragma unroll
            for (int nt = 0; nt < 4; nt++) {
                mma_tf32(d[mt][nt], ah[mt], bh[nt]);
                mma_tf32(d[mt][nt], ah[mt], bl[nt]);
                mma_tf32(d[mt][nt], al[mt], bh[nt]);
            }

        if (tk + 1 < ktiles) {
            int nb = buf ^ 1;
            unsigned* ah4 = (unsigned*)&avh; unsigned* al4 = (unsigned*)&avl;
#pragma unroll
            for (int j = 0; j < 4; j++) {
                Ah[nb][kq + j][m2a] = ah4[j];
                Al[nb][kq + j][m2a] = al4[j];
            }
            BFh[nb][bwc0][bnt0][bl0] = bvh.x; BFl[nb][bwc0][bnt0][bl0] = bvl.x;
            BFh[nb][bwc1][bnt1][bl1] = bvh.y; BFl[nb][bwc1][bnt1][bl1] = bvl.y;
        }
        __syncthreads();
    }

    int wn = wc * 32;
#pragma unroll
    for (int mt = 0; mt < 2; mt++) {
#pragma unroll
        for (int nt = 0; nt < 4; nt++) {
            int r0 = m0 + wm + mt * 16 + g;
            int cc = n0 + wn + nt * 8 + 2 * tig;
            float2 lo = { d[mt][nt][0], d[mt][nt][1] };
            float2 hi = { d[mt][nt][2], d[mt][nt][3] };
            *reinterpret_cast<float2*>(&C[(size_t)r0 * N + cc])       = lo;
            *reinterpret_cast<float2*>(&C[(size_t)(r0 + 8) * N + cc]) = hi;
        }
    }

    if (SCORES) {
#pragma unroll
        for (int mt = 0; mt < 2; mt++) {
#pragma unroll
            for (int h = 0; h < 2; h++) {
                float l1 = 0.f, l2 = 0.f;
#pragma unroll
                for (int nt = 0; nt < 4; nt++) {
                    int cc = n0 + wn + nt * 8 + 2 * tig;
                    float c0 = d[mt][nt][2 * h], c1 = d[mt][nt][2 * h + 1];
                    l1 += c0 * avec[cc] + c1 * avec[cc + 1];
                    l2 += c0 * avec[DOUT + cc] + c1 * avec[DOUT + cc + 1];
                }
                l1 += __shfl_xor_sync(FULL, l1, 1);
                l1 += __shfl_xor_sync(FULL, l1, 2);
                l2 += __shfl_xor_sync(FULL, l2, 1);
                l2 += __shfl_xor_sync(FULL, l2, 2);
                if (tig == 0) {
                    int rl = wm + mt * 16 + g + 8 * h;
                    sc1[rl][wc] = l1;
                    sc2[rl][wc] = l2;
                }
            }
        }
        __syncthreads();
        if (tid < 128) {
            g_s1p[blockIdx.x][m0 + tid] = sc1[tid][0] + sc1[tid][1];
            g_s2p[blockIdx.x][m0 + tid] = sc2[tid][0] + sc2[tid][1];
        }
    }
}

// ---------------------------------------------------------------------------
// Build padded CSR. One block/row, 256 thr, coalesced strided loads.
// ---------------------------------------------------------------------------
__global__ void build_csr(const float* __restrict__ adj) {
    int row = blockIdx.x;
    int t   = threadIdx.x;
    int lane = t & 31, warp = t >> 5;
    const float4* arow = reinterpret_cast<const float4*>(adj + (size_t)row * NN);

    float4 v[8];
    int cnt = 0;
#pragma unroll
    for (int i = 0; i < 8; i++) {
        v[i] = arow[t + i * 256];
        cnt += (v[i].x > 0.f) + (v[i].y > 0.f) + (v[i].z > 0.f) + (v[i].w > 0.f);
    }

    int inc = cnt;
#pragma unroll
    for (int o = 1; o < 32; o <<= 1) {
        int u = __shfl_up_sync(FULL, inc, o);
        if (lane >= o) inc += u;
    }
    __shared__ int wsum[8], wbase[8];
    if (lane == 31) wsum[warp] = inc;
    __syncthreads();
    if (t == 0) {
        int run = 0;
#pragma unroll
        for (int w = 0; w < 8; w++) { wbase[w] = run; run += wsum[w]; }
        g_nnz[row] = run < CAP ? run : CAP;
    }
    __syncthreads();

    int pos = wbase[warp] + inc - cnt;
    int*   cr = g_cols + (size_t)row * CAP;
    float* vr = g_vals + (size_t)row * CAP;
#pragma unroll
    for (int i = 0; i < 8; i++) {
        int base = (t + i * 256) * 4;
        float vv[4] = { v[i].x, v[i].y, v[i].z, v[i].w };
#pragma unroll
        for (int j = 0; j < 4; j++) {
            if (vv[j] > 0.f) {
                if (pos < CAP) { cr[pos] = base + j; vr[pos] = vv[j]; }
                pos++;
            }
        }
    }
}

// ---------------------------------------------------------------------------
// Barrier-free SpMM + bias + leaky; emits tf32 hi/lo pairs directly.
// ---------------------------------------------------------------------------
__global__ __launch_bounds__(128) void spmm_leaky(
    const float* __restrict__ T, const float* __restrict__ bias,
    unsigned* __restrict__ Oh, unsigned* __restrict__ Ol)
{
    int row = blockIdx.x * 2 + (threadIdx.x >> 6);
    int l   = threadIdx.x & 63;
    int nnz = g_nnz[row];
    const int*   cp = g_cols + (size_t)row * CAP;
    const float* vp = g_vals + (size_t)row * CAP;

    float4 a0 = {0,0,0,0}, a1 = {0,0,0,0}, a2 = {0,0,0,0}, a3 = {0,0,0,0};
    int k = 0;
    for (; k + 3 < nnz; k += 4) {
        int   c0 = cp[k], c1 = cp[k+1], c2 = cp[k+2], c3 = cp[k+3];
        float w0 = vp[k], w1 = vp[k+1], w2 = vp[k+2], w3 = vp[k+3];
        float4 v0 = reinterpret_cast<const float4*>(T + (size_t)c0 * DH)[l];
        float4 v1 = reinterpret_cast<const float4*>(T + (size_t)c1 * DH)[l];
        float4 v2 = reinterpret_cast<const float4*>(T + (size_t)c2 * DH)[l];
        float4 v3 = reinterpret_cast<const float4*>(T + (size_t)c3 * DH)[l];
        a0.x += w0*v0.x; a0.y += w0*v0.y; a0.z += w0*v0.z; a0.w += w0*v0.w;
        a1.x += w1*v1.x; a1.y += w1*v1.y; a1.z += w1*v1.z; a1.w += w1*v1.w;
        a2.x += w2*v2.x; a2.y += w2*v2.y; a2.z += w2*v2.z; a2.w += w2*v2.w;
        a3.x += w3*v3.x; a3.y += w3*v3.y; a3.z += w3*v3.z; a3.w += w3*v3.w;
    }
    for (; k < nnz; k++) {
        int c0 = cp[k]; float w0 = vp[k];
        float4 v0 = reinterpret_cast<const float4*>(T + (size_t)c0 * DH)[l];
        a0.x += w0*v0.x; a0.y += w0*v0.y; a0.z += w0*v0.z; a0.w += w0*v0.w;
    }
    float4 b = reinterpret_cast<const float4*>(bias)[l];
    float4 o;
    o.x = leaky(a0.x + a1.x + a2.x + a3.x + b.x);
    o.y = leaky(a0.y + a1.y + a2.y + a3.y + b.y);
    o.z = leaky(a0.z + a1.z + a2.z + a3.z + b.z);
    o.w = leaky(a0.w + a1.w + a2.w + a3.w + b.w);
    uint4 hh, ll;
    hh.x = f2tf32(o.x); ll.x = f2tf32(o.x - __uint_as_float(hh.x));
    hh.y = f2tf32(o.y); ll.y = f2tf32(o.y - __uint_as_float(hh.y));
    hh.z = f2tf32(o.z); ll.z = f2tf32(o.z - __uint_as_float(hh.z));
    hh.w = f2tf32(o.w); ll.w = f2tf32(o.w - __uint_as_float(hh.w));
    reinterpret_cast<uint4*>(Oh + (size_t)row * DH)[l] = hh;
    reinterpret_cast<uint4*>(Ol + (size_t)row * DH)[l] = ll;
}

// ---------------------------------------------------------------------------
// Warp-per-row sparse attention (exact match of dense masked softmax).
// ---------------------------------------------------------------------------
__global__ __launch_bounds__(256) void attn_k(float* __restrict__ out) {
    int warp = threadIdx.x >> 5, l = threadIdx.x & 31;
    int row  = blockIdx.x * 8 + warp;
    int nnz  = g_nnz[row];

    __shared__ float sw[8][CAP];
    __shared__ int   sc[8][CAP];
    float* w = sw[warp];
    int*   c = sc[warp];

    float4 o;
    if (nnz == 0) {
        float4 s = {0,0,0,0};
        for (int r = 0; r < NN; r++) {
            float4 hv = reinterpret_cast<const float4*>(g_h + (size_t)r * DOUT)[l];
            s.x += hv.x; s.y += hv.y; s.z += hv.z; s.w += hv.w;
        }
        float inv = 1.f / (float)NN;
        o.x = leaky(s.x * inv); o.y = leaky(s.y * inv);
        o.z = leaky(s.z * inv); o.w = leaky(s.w * inv);
    } else {
        float s1i = g_s1p[0][row] + g_s1p[1][row];
        const int* cp = g_cols + (size_t)row * CAP;
        float m = -3.0e38f;
        for (int k = l; k < nnz; k += 32) {
            int cj = cp[k];
            float e = leaky(s1i + (g_s2p[0][cj] + g_s2p[1][cj]));
            c[k] = cj; w[k] = e;
            m = fmaxf(m, e);
        }
        __syncwarp();
#pragma unroll
        for (int off = 16; off > 0; off >>= 1)
            m = fmaxf(m, __shfl_xor_sync(FULL, m, off));
        float s = 0.f;
        for (int k = l; k < nnz; k += 32) {
            float e = expf(w[k] - m);
            w[k] = e; s += e;
        }
        __syncwarp();
#pragma unroll
        for (int off = 16; off > 0; off >>= 1)
            s += __shfl_xor_sync(FULL, s, off);
        float inv = 1.f / s;

        float4 a0 = {0,0,0,0}, a1 = {0,0,0,0};
        int k = 0;
        for (; k + 1 < nnz; k += 2) {
            float w0 = w[k], w1 = w[k+1];
            float4 v0 = reinterpret_cast<const float4*>(g_h + (size_t)c[k]   * DOUT)[l];
            float4 v1 = reinterpret_cast<const float4*>(g_h + (size_t)c[k+1] * DOUT)[l];
            a0.x += w0*v0.x; a0.y += w0*v0.y; a0.z += w0*v0.z; a0.w += w0*v0.w;
            a1.x += w1*v1.x; a1.y += w1*v1.y; a1.z += w1*v1.z; a1.w += w1*v1.w;
        }
        if (k < nnz) {
            float w0 = w[k];
            float4 v0 = reinterpret_cast<const float4*>(g_h + (size_t)c[k] * DOUT)[l];
            a0.x += w0*v0.x; a0.y += w0*v0.y; a0.z += w0*v0.z; a0.w += w0*v0.w;
        }
        o.x = leaky((a0.x + a1.x) * inv);
        o.y = leaky((a0.y + a1.y) * inv);
        o.z = leaky((a0.z + a1.z) * inv);
        o.w = leaky((a0.w + a1.w) * inv);
    }
    if (l < 16)
        *reinterpret_cast<float4*>(out + (size_t)row * 64 + l * 4) = o;
    else
        *reinterpret_cast<float4*>(out + (size_t)NN * 64 + (size_t)row * 64 + (l * 4 - 64)) = o;
}

// ---------------------------------------------------------------------------
extern "C" void kernel_launch(void* const* d_in, const int* in_sizes, int n_in,
                              void* d_out, int out_size)
{
    const float* x   = (const float*)d_in[0];
    const float* adj = (const float*)d_in[1];
    const float* W1  = (const float*)d_in[2];
    const float* b1  = (const float*)d_in[3];
    const float* W2  = (const float*)d_in[4];
    const float* b2  = (const float*)d_in[5];
    const float* Wg  = (const float*)d_in[6];
    const float* a   = (const float*)d_in[7];

    float *pT, *pH;
    unsigned *pxh, *pxl, *pw1h, *pw1l, *pw2h, *pw2l, *pwgh, *pwgl, *poph, *popl;
    cudaGetSymbolAddress((void**)&pT,   g_t);
    cudaGetSymbolAddress((void**)&pH,   g_h);
    cudaGetSymbolAddress((void**)&pxh,  g_xh);
    cudaGetSymbolAddress((void**)&pxl,  g_xl);
    cudaGetSymbolAddress((void**)&pw1h, g_W1h);
    cudaGetSymbolAddress((void**)&pw1l, g_W1l);
    cudaGetSymbolAddress((void**)&pw2h, g_W2h);
    cudaGetSymbolAddress((void**)&pw2l, g_W2l);
    cudaGetSymbolAddress((void**)&pwgh, g_Wgh);
    cudaGetSymbolAddress((void**)&pwgl, g_Wgl);
    cudaGetSymbolAddress((void**)&poph, g_oph);
    cudaGetSymbolAddress((void**)&popl, g_opl);

    build_csr<<<NN, 256>>>(adj);
    cvt_split<<<CVT_BLOCKS, 256>>>((const float4*)x, (const float4*)W1,
                                   (const float4*)W2, (const float4*)Wg);
    // t1 = x @ W1
    gemm_tf32<false><<<dim3(DH / 64, NN / 128), 256>>>(
        pxh, pxl, pw1h, pw1l, pT, DIN, DH, nullptr);
    // x1 = leaky(adj @ t1 + b1) -> hi/lo
    spmm_leaky<<<NN / 2, 128>>>(pT, b1, poph, popl);
    // t2 = x1 @ W2
    gemm_tf32<false><<<dim3(DH / 64, NN / 128), 256>>>(
        poph, popl, pw2h, pw2l, pT, DH, DH, nullptr);
    // x2 = leaky(adj @ t2 + b2) -> hi/lo
    spmm_leaky<<<NN / 2, 128>>>(pT, b2, poph, popl);
    // h = x2 @ Wg + fused per-half s1/s2 scores
    gemm_tf32<true><<<dim3(2, NN / 128), 256>>>(
        poph, popl, pwgh, pwgl, pH, DH, DOUT, a);
    // softmax-weighted gather + output
    attn_k<<<NN / 8, 256>>>((float*)d_out);
}

// round 15
// speedup vs baseline: 1.2924x; 1.0931x over previous
#include <cuda_runtime.h>
#include <cstdint>
#include <cstddef>

#define NN   8192
#define DIN  512
#define DH   256
#define DOUT 128
#define CAP  256
#define SLOPE 0.25f
#define FULL 0xffffffffu

// ---- scratch (static device globals; no allocation allowed) ----
__device__ int   g_cols[(size_t)NN * CAP];
__device__ float g_vals[(size_t)NN * CAP];
__device__ int   g_nnz[NN];
__device__ float g_bufA[(size_t)NN * DH];
__device__ float g_bufB[(size_t)NN * DH];
__device__ float g_h[(size_t)NN * DOUT];
__device__ float g_s1p[2][NN];
__device__ float g_s2p[2][NN];

__device__ __forceinline__ float leaky(float x) { return x >= 0.f ? x : SLOPE * x; }

__device__ __forceinline__ unsigned f2tf32(float x) {
    unsigned r;
    asm("cvt.rna.tf32.f32 %0, %1;" : "=r"(r) : "f"(x));
    return r;
}

__device__ __forceinline__ void mma_tf32(float* d, const unsigned* a, const unsigned* b) {
    asm volatile(
        "mma.sync.aligned.m16n8k8.row.col.f32.tf32.tf32.f32 "
        "{%0,%1,%2,%3}, {%4,%5,%6,%7}, {%8,%9}, {%0,%1,%2,%3};"
        : "+f"(d[0]), "+f"(d[1]), "+f"(d[2]), "+f"(d[3])
        : "r"(a[0]), "r"(a[1]), "r"(a[2]), "r"(a[3]), "r"(b[0]), "r"(b[1]));
}

// ---------------------------------------------------------------------------
// 3xTF32 tensor-core GEMM (proven R12 version): CTA 128x64, 8 warps (4m x 2n),
// warp tile 32x32 (2x4 m16n8k8), BK=8, double-buffered, in-loop hi/lo cvt.
// ---------------------------------------------------------------------------
template<bool SCORES>
__global__ __launch_bounds__(256) void gemm_tf32(
    const float* __restrict__ A, const float* __restrict__ B,
    float* __restrict__ C, int K, int N, const float* __restrict__ avec)
{
    __shared__ unsigned Ah[2][8][136], Al[2][8][136];   // [buf][k][m], stride 136%32==8
    __shared__ unsigned Bh[2][8][72],  Bl[2][8][72];    // [buf][k][n], stride  72%32==8
    __shared__ float sc1[128][2], sc2[128][2];

    int tid  = threadIdx.x;
    int warp = tid >> 5, lane = tid & 31;
    int g = lane >> 2, tig = lane & 3;
    int wm = (warp >> 1) * 32, wn = (warp & 1) * 32;
    int m0 = blockIdx.y * 128, n0 = blockIdx.x * 64;

    int arow = tid >> 1, kq = (tid & 1) * 4;
    const float* Aptr = A + (size_t)(m0 + arow) * K + kq;
    int brow = tid >> 5, bn = (tid & 31) * 2;
    const float* Bptr = B + (size_t)brow * N + n0 + bn;

    float4 av = *reinterpret_cast<const float4*>(Aptr);
    float2 bv = *reinterpret_cast<const float2*>(Bptr);
    {
        float ax[4] = { av.x, av.y, av.z, av.w };
#pragma unroll
        for (int j = 0; j < 4; j++) {
            unsigned h = f2tf32(ax[j]);
            Ah[0][kq + j][arow] = h;
            Al[0][kq + j][arow] = f2tf32(ax[j] - __uint_as_float(h));
        }
        float bx2[2] = { bv.x, bv.y };
#pragma unroll
        for (int j = 0; j < 2; j++) {
            unsigned h = f2tf32(bx2[j]);
            Bh[0][brow][bn + j] = h;
            Bl[0][brow][bn + j] = f2tf32(bx2[j] - __uint_as_float(h));
        }
    }
    __syncthreads();

    float d[2][4][4];
#pragma unroll
    for (int mt = 0; mt < 2; mt++)
#pragma unroll
        for (int nt = 0; nt < 4; nt++)
#pragma unroll
            for (int i = 0; i < 4; i++) d[mt][nt][i] = 0.f;

    int ktiles = K >> 3;
    for (int tk = 0; tk < ktiles; tk++) {
        int buf = tk & 1;
        if (tk + 1 < ktiles) {
            av = *reinterpret_cast<const float4*>(Aptr + (tk + 1) * 8);
            bv = *reinterpret_cast<const float2*>(Bptr + (size_t)(tk + 1) * 8 * N);
        }

        unsigned ah[2][4], al[2][4], bh[4][2], bl[4][2];
#pragma unroll
        for (int mt = 0; mt < 2; mt++) {
            int r = wm + mt * 16 + g;
            ah[mt][0] = Ah[buf][tig][r];     al[mt][0] = Al[buf][tig][r];
            ah[mt][1] = Ah[buf][tig][r + 8]; al[mt][1] = Al[buf][tig][r + 8];
            ah[mt][2] = Ah[buf][tig + 4][r];     al[mt][2] = Al[buf][tig + 4][r];
            ah[mt][3] = Ah[buf][tig + 4][r + 8]; al[mt][3] = Al[buf][tig + 4][r + 8];
        }
#pragma unroll
        for (int nt = 0; nt < 4; nt++) {
            int c = wn + nt * 8 + g;
            bh[nt][0] = Bh[buf][tig][c];     bl[nt][0] = Bl[buf][tig][c];
            bh[nt][1] = Bh[buf][tig + 4][c]; bl[nt][1] = Bl[buf][tig + 4][c];
        }
#pragma unroll
        for (int mt = 0; mt < 2; mt++)
#pragma unroll
            for (int nt = 0; nt < 4; nt++) {
                mma_tf32(d[mt][nt], ah[mt], bh[nt]);
                mma_tf32(d[mt][nt], ah[mt], bl[nt]);
                mma_tf32(d[mt][nt], al[mt], bh[nt]);
            }

        if (tk + 1 < ktiles) {
            int nb = buf ^ 1;
            float ax[4] = { av.x, av.y, av.z, av.w };
#pragma unroll
            for (int j = 0; j < 4; j++) {
                unsigned h = f2tf32(ax[j]);
                Ah[nb][kq + j][arow] = h;
                Al[nb][kq + j][arow] = f2tf32(ax[j] - __uint_as_float(h));
            }
            float bx2[2] = { bv.x, bv.y };
#pragma unroll
            for (int j = 0; j < 2; j++) {
                unsigned h = f2tf32(bx2[j]);
                Bh[nb][brow][bn + j] = h;
                Bl[nb][brow][bn + j] = f2tf32(bx2[j] - __uint_as_float(h));
            }
        }
        __syncthreads();
    }

#pragma unroll
    for (int mt = 0; mt < 2; mt++) {
#pragma unroll
        for (int nt = 0; nt < 4; nt++) {
            int r0 = m0 + wm + mt * 16 + g;
            int cc = n0 + wn + nt * 8 + 2 * tig;
            float2 lo = { d[mt][nt][0], d[mt][nt][1] };
            float2 hi = { d[mt][nt][2], d[mt][nt][3] };
            *reinterpret_cast<float2*>(&C[(size_t)r0 * N + cc])       = lo;
            *reinterpret_cast<float2*>(&C[(size_t)(r0 + 8) * N + cc]) = hi;
        }
    }

    if (SCORES) {
#pragma unroll
        for (int mt = 0; mt < 2; mt++) {
#pragma unroll
            for (int h = 0; h < 2; h++) {
                float l1 = 0.f, l2 = 0.f;
#pragma unroll
                for (int nt = 0; nt < 4; nt++) {
                    int cc = n0 + wn + nt * 8 + 2 * tig;
                    float c0 = d[mt][nt][2 * h], c1 = d[mt][nt][2 * h + 1];
                    l1 += c0 * avec[cc] + c1 * avec[cc + 1];
                    l2 += c0 * avec[DOUT + cc] + c1 * avec[DOUT + cc + 1];
                }
                l1 += __shfl_xor_sync(FULL, l1, 1);
                l1 += __shfl_xor_sync(FULL, l1, 2);
                l2 += __shfl_xor_sync(FULL, l2, 1);
                l2 += __shfl_xor_sync(FULL, l2, 2);
                if (tig == 0) {
                    int rl = wm + mt * 16 + g + 8 * h;
                    sc1[rl][warp & 1] = l1;
                    sc2[rl][warp & 1] = l2;
                }
            }
        }
        __syncthreads();
        if (tid < 128) {
            g_s1p[blockIdx.x][m0 + tid] = sc1[tid][0] + sc1[tid][1];
            g_s2p[blockIdx.x][m0 + tid] = sc2[tid][0] + sc2[tid][1];
        }
    }
}

// ---------------------------------------------------------------------------
// Build padded CSR. One block/row, 256 thr, coalesced strided loads.
// NEW: emit phase skips all-zero float4 groups via a 3-op fmax tree
// (~98% of per-thread iterations collapse; output bit-identical).
// ---------------------------------------------------------------------------
__global__ void build_csr(const float* __restrict__ adj) {
    int row = blockIdx.x;
    int t   = threadIdx.x;
    int lane = t & 31, warp = t >> 5;
    const float4* arow = reinterpret_cast<const float4*>(adj + (size_t)row * NN);

    float4 v[8];
    int cnt = 0;
#pragma unroll
    for (int i = 0; i < 8; i++) {
        v[i] = arow[t + i * 256];
        cnt += (v[i].x > 0.f) + (v[i].y > 0.f) + (v[i].z > 0.f) + (v[i].w > 0.f);
    }

    int inc = cnt;
#pragma unroll
    for (int o = 1; o < 32; o <<= 1) {
        int u = __shfl_up_sync(FULL, inc, o);
        if (lane >= o) inc += u;
    }
    __shared__ int wsum[8], wbase[8];
    if (lane == 31) wsum[warp] = inc;
    __syncthreads();
    if (t == 0) {
        int run = 0;
#pragma unroll
        for (int w = 0; w < 8; w++) { wbase[w] = run; run += wsum[w]; }
        g_nnz[row] = run < CAP ? run : CAP;
    }
    __syncthreads();

    int pos = wbase[warp] + inc - cnt;
    int*   cr = g_cols + (size_t)row * CAP;
    float* vr = g_vals + (size_t)row * CAP;
#pragma unroll
    for (int i = 0; i < 8; i++) {
        float mx = fmaxf(fmaxf(v[i].x, v[i].y), fmaxf(v[i].z, v[i].w));
        if (mx > 0.f) {
            int base = (t + i * 256) * 4;
            float vv[4] = { v[i].x, v[i].y, v[i].z, v[i].w };
#pragma unroll
            for (int j = 0; j < 4; j++) {
                if (vv[j] > 0.f) {
                    if (pos < CAP) { cr[pos] = base + j; vr[pos] = vv[j]; }
                    pos++;
                }
            }
        }
    }
}

// ---------------------------------------------------------------------------
// Barrier-free SpMM + bias + leaky. 64 lanes/row (float4), 2 rows per block.
// At the L2 gather roofline.
// ---------------------------------------------------------------------------
__global__ __launch_bounds__(128) void spmm_leaky(
    const float* __restrict__ T, const float* __restrict__ bias,
    float* __restrict__ O)
{
    int row = blockIdx.x * 2 + (threadIdx.x >> 6);
    int l   = threadIdx.x & 63;
    int nnz = g_nnz[row];
    const int*   cp = g_cols + (size_t)row * CAP;
    const float* vp = g_vals + (size_t)row * CAP;

    float4 a0 = {0,0,0,0}, a1 = {0,0,0,0}, a2 = {0,0,0,0}, a3 = {0,0,0,0};
    int k = 0;
    for (; k + 3 < nnz; k += 4) {
        int   c0 = cp[k], c1 = cp[k+1], c2 = cp[k+2], c3 = cp[k+3];
        float w0 = vp[k], w1 = vp[k+1], w2 = vp[k+2], w3 = vp[k+3];
        float4 v0 = reinterpret_cast<const float4*>(T + (size_t)c0 * DH)[l];
        float4 v1 = reinterpret_cast<const float4*>(T + (size_t)c1 * DH)[l];
        float4 v2 = reinterpret_cast<const float4*>(T + (size_t)c2 * DH)[l];
        float4 v3 = reinterpret_cast<const float4*>(T + (size_t)c3 * DH)[l];
        a0.x += w0*v0.x; a0.y += w0*v0.y; a0.z += w0*v0.z; a0.w += w0*v0.w;
        a1.x += w1*v1.x; a1.y += w1*v1.y; a1.z += w1*v1.z; a1.w += w1*v1.w;
        a2.x += w2*v2.x; a2.y += w2*v2.y; a2.z += w2*v2.z; a2.w += w2*v2.w;
        a3.x += w3*v3.x; a3.y += w3*v3.y; a3.z += w3*v3.z; a3.w += w3*v3.w;
    }
    for (; k < nnz; k++) {
        int c0 = cp[k]; float w0 = vp[k];
        float4 v0 = reinterpret_cast<const float4*>(T + (size_t)c0 * DH)[l];
        a0.x += w0*v0.x; a0.y += w0*v0.y; a0.z += w0*v0.z; a0.w += w0*v0.w;
    }
    float4 b = reinterpret_cast<const float4*>(bias)[l];
    float4 o;
    o.x = leaky(a0.x + a1.x + a2.x + a3.x + b.x);
    o.y = leaky(a0.y + a1.y + a2.y + a3.y + b.y);
    o.z = leaky(a0.z + a1.z + a2.z + a3.z + b.z);
    o.w = leaky(a0.w + a1.w + a2.w + a3.w + b.w);
    reinterpret_cast<float4*>(O + (size_t)row * DH)[l] = o;
}

// ---------------------------------------------------------------------------
// Warp-per-row sparse attention (exact match of dense masked softmax).
// ---------------------------------------------------------------------------
__global__ __launch_bounds__(256) void attn_k(float* __restrict__ out) {
    int warp = threadIdx.x >> 5, l = threadIdx.x & 31;
    int row  = blockIdx.x * 8 + warp;
    int nnz  = g_nnz[row];

    __shared__ float sw[8][CAP];
    __shared__ int   sc[8][CAP];
    float* w = sw[warp];
    int*   c = sc[warp];

    float4 o;
    if (nnz == 0) {
        float4 s = {0,0,0,0};
        for (int r = 0; r < NN; r++) {
            float4 hv = reinterpret_cast<const float4*>(g_h + (size_t)r * DOUT)[l];
            s.x += hv.x; s.y += hv.y; s.z += hv.z; s.w += hv.w;
        }
        float inv = 1.f / (float)NN;
        o.x = leaky(s.x * inv); o.y = leaky(s.y * inv);
        o.z = leaky(s.z * inv); o.w = leaky(s.w * inv);
    } else {
        float s1i = g_s1p[0][row] + g_s1p[1][row];
        const int* cp = g_cols + (size_t)row * CAP;
        float m = -3.0e38f;
        for (int k = l; k < nnz; k += 32) {
            int cj = cp[k];
            float e = leaky(s1i + (g_s2p[0][cj] + g_s2p[1][cj]));
            c[k] = cj; w[k] = e;
            m = fmaxf(m, e);
        }
        __syncwarp();
#pragma unroll
        for (int off = 16; off > 0; off >>= 1)
            m = fmaxf(m, __shfl_xor_sync(FULL, m, off));
        float s = 0.f;
        for (int k = l; k < nnz; k += 32) {
            float e = expf(w[k] - m);
            w[k] = e; s += e;
        }
        __syncwarp();
#pragma unroll
        for (int off = 16; off > 0; off >>= 1)
            s += __shfl_xor_sync(FULL, s, off);
        float inv = 1.f / s;

        float4 a0 = {0,0,0,0}, a1 = {0,0,0,0};
        int k = 0;
        for (; k + 1 < nnz; k += 2) {
            float w0 = w[k], w1 = w[k+1];
            float4 v0 = reinterpret_cast<const float4*>(g_h + (size_t)c[k]   * DOUT)[l];
            float4 v1 = reinterpret_cast<const float4*>(g_h + (size_t)c[k+1] * DOUT)[l];
            a0.x += w0*v0.x; a0.y += w0*v0.y; a0.z += w0*v0.z; a0.w += w0*v0.w;
            a1.x += w1*v1.x; a1.y += w1*v1.y; a1.z += w1*v1.z; a1.w += w1*v1.w;
        }
        if (k < nnz) {
            float w0 = w[k];
            float4 v0 = reinterpret_cast<const float4*>(g_h + (size_t)c[k] * DOUT)[l];
            a0.x += w0*v0.x; a0.y += w0*v0.y; a0.z += w0*v0.z; a0.w += w0*v0.w;
        }
        o.x = leaky((a0.x + a1.x) * inv);
        o.y = leaky((a0.y + a1.y) * inv);
        o.z = leaky((a0.z + a1.z) * inv);
        o.w = leaky((a0.w + a1.w) * inv);
    }
    if (l < 16)
        *reinterpret_cast<float4*>(out + (size_t)row * 64 + l * 4) = o;
    else
        *reinterpret_cast<float4*>(out + (size_t)NN * 64 + (size_t)row * 64 + (l * 4 - 64)) = o;
}

// ---------------------------------------------------------------------------
extern "C" void kernel_launch(void* const* d_in, const int* in_sizes, int n_in,
                              void* d_out, int out_size)
{
    const float* x   = (const float*)d_in[0];
    const float* adj = (const float*)d_in[1];
    const float* W1  = (const float*)d_in[2];
    const float* b1  = (const float*)d_in[3];
    const float* W2  = (const float*)d_in[4];
    const float* b2  = (const float*)d_in[5];
    const float* Wg  = (const float*)d_in[6];
    const float* a   = (const float*)d_in[7];

    float *pA, *pB, *pH;
    cudaGetSymbolAddress((void**)&pA, g_bufA);
    cudaGetSymbolAddress((void**)&pB, g_bufB);
    cudaGetSymbolAddress((void**)&pH, g_h);

    build_csr<<<NN, 256>>>(adj);
    // t1 = x @ W1
    gemm_tf32<false><<<dim3(DH / 64, NN / 128), 256>>>(x, W1, pA, DIN, DH, nullptr);
    // x1 = leaky(adj @ t1 + b1)
    spmm_leaky<<<NN / 2, 128>>>(pA, b1, pB);
    // t2 = x1 @ W2
    gemm_tf32<false><<<dim3(DH / 64, NN / 128), 256>>>(pB, W2, pA, DH, DH, nullptr);
    // x2 = leaky(adj @ t2 + b2)
    spmm_leaky<<<NN / 2, 128>>>(pA, b2, pB);
    // h = x2 @ Wg + fused per-half s1/s2 scores
    gemm_tf32<true><<<dim3(2, NN / 128), 256>>>(pB, Wg, pH, DH, DOUT, a);
    // softmax-weighted gather + output
    attn_k<<<NN / 8, 256>>>((float*)d_out);
}